// round 17
// baseline (speedup 1.0000x reference)
#include <cuda_runtime.h>
#include <cuda_fp16.h>

#define BB 4
#define NN 4096
#define DD 64

// ---------------- scratch (device globals; no allocation allowed) ----------
// bit-packed A, bytes permuted for fast fragment spread:
// byte t of each word = orig bits {2t,2t+1, 2t+8,2t+9, 2t+16,2t+17, 2t+24,2t+25}
__device__ __align__(16) unsigned g_Ap[(size_t)BB * NN * (NN / 32)];
__device__ float g_dinv[BB * NN];
// ping-pong fp16 feature buffers, row-major [b][j][d], pre-scaled by dinv_j
__device__ __align__(16) __half g_tb[2][(size_t)BB * NN * DD];

// ---------------- threefry2x32 (Random123 / JAX) ---------------------------
__host__ __device__ constexpr unsigned rotl32(unsigned x, int r) {
  return (x << r) | (x >> (32 - r));
}

__host__ __device__ constexpr void tf2x32(unsigned k0, unsigned k1,
                                          unsigned& x0, unsigned& x1) {
  unsigned k2 = k0 ^ k1 ^ 0x1BD11BDAu;
  x0 += k0; x1 += k1;
  x0+=x1; x1=rotl32(x1,13); x1^=x0;
  x0+=x1; x1=rotl32(x1,15); x1^=x0;
  x0+=x1; x1=rotl32(x1,26); x1^=x0;
  x0+=x1; x1=rotl32(x1, 6); x1^=x0;
  x0+=k1; x1+=k2+1u;
  x0+=x1; x1=rotl32(x1,17); x1^=x0;
  x0+=x1; x1=rotl32(x1,29); x1^=x0;
  x0+=x1; x1=rotl32(x1,16); x1^=x0;
  x0+=x1; x1=rotl32(x1,24); x1^=x0;
  x0+=k2; x1+=k0+2u;
  x0+=x1; x1=rotl32(x1,13); x1^=x0;
  x0+=x1; x1=rotl32(x1,15); x1^=x0;
  x0+=x1; x1=rotl32(x1,26); x1^=x0;
  x0+=x1; x1=rotl32(x1, 6); x1^=x0;
  x0+=k0; x1+=k1+3u;
  x0+=x1; x1=rotl32(x1,17); x1^=x0;
  x0+=x1; x1=rotl32(x1,29); x1^=x0;
  x0+=x1; x1=rotl32(x1,16); x1^=x0;
  x0+=x1; x1=rotl32(x1,24); x1^=x0;
  x0+=k1; x1+=k2+4u;
  x0+=x1; x1=rotl32(x1,13); x1^=x0;
  x0+=x1; x1=rotl32(x1,15); x1^=x0;
  x0+=x1; x1=rotl32(x1,26); x1^=x0;
  x0+=x1; x1=rotl32(x1, 6); x1^=x0;
  x0+=k2; x1+=k0+5u;
}

struct KeyPair { unsigned a, b; };
__host__ __device__ constexpr KeyPair derive_key(unsigned ctr) {
  unsigned x0 = 0u, x1 = ctr;
  tf2x32(0u, 42u, x0, x1);
  return KeyPair{x0, x1};
}
constexpr KeyPair cK1 = derive_key(0u);
constexpr KeyPair cK2 = derive_key(1u);

__device__ __forceinline__ float drop_apply(float v, unsigned idx,
                                            unsigned ka, unsigned kb) {
  unsigned y0 = 0u, y1 = idx;
  tf2x32(ka, kb, y0, y1);
  unsigned bits = y0 ^ y1;
  float u = __uint_as_float((bits >> 9) | 0x3f800000u) - 1.0f;
  return (u < 0.8f) ? v * 1.25f : 0.0f;
}

// ---------------- mma / async helpers (baseline sm_103-safe) ----------------
__device__ __forceinline__ unsigned smem_u32(const void* p) {
  unsigned r;
  asm("{ .reg .u64 t; cvta.to.shared.u64 t, %1; cvt.u32.u64 %0, t; }"
      : "=r"(r) : "l"(p));
  return r;
}
__device__ __forceinline__ void ldsm_x4a(unsigned* r, unsigned addr) {
  asm volatile("ldmatrix.sync.aligned.m8n8.x4.shared.b16 {%0,%1,%2,%3}, [%4];"
               : "=r"(r[0]), "=r"(r[1]), "=r"(r[2]), "=r"(r[3]) : "r"(addr));
}
__device__ __forceinline__ void ldsm_x4ta(unsigned* r, unsigned addr) {
  asm volatile("ldmatrix.sync.aligned.m8n8.x4.trans.shared.b16 {%0,%1,%2,%3}, [%4];"
               : "=r"(r[0]), "=r"(r[1]), "=r"(r[2]), "=r"(r[3]) : "r"(addr));
}
__device__ __forceinline__ void ldsm_x4(unsigned* r, const void* p) {
  ldsm_x4a(r, smem_u32(p));
}
__device__ __forceinline__ void ldsm_x4_t(unsigned* r, const void* p) {
  ldsm_x4ta(r, smem_u32(p));
}
__device__ __forceinline__ void mma16816(float* c, const unsigned* a,
                                         unsigned b0, unsigned b1) {
  asm volatile(
      "mma.sync.aligned.m16n8k16.row.col.f32.f16.f16.f32 "
      "{%0,%1,%2,%3}, {%4,%5,%6,%7}, {%8,%9}, {%0,%1,%2,%3};"
      : "+f"(c[0]), "+f"(c[1]), "+f"(c[2]), "+f"(c[3])
      : "r"(a[0]), "r"(a[1]), "r"(a[2]), "r"(a[3]), "r"(b0), "r"(b1));
}
__device__ __forceinline__ void cp16(unsigned dst, const void* src) {
  asm volatile("cp.async.cg.shared.global [%0], [%1], 16;"
               :: "r"(dst), "l"(src) : "memory");
}
__device__ __forceinline__ void cp_commit() {
  asm volatile("cp.async.commit_group;" ::: "memory");
}
__device__ __forceinline__ void cp_wait0() {
  asm volatile("cp.async.wait_group 0;" ::: "memory");
}

// ---------------- kernel 1: degrees + permuted bit-packed A + scaled x ------
// adj values are exactly {0,1} (randint(0,2)) -> pack with IMAD chain;
// byte-permute done as 4x4 pair-transpose (2 delta swaps, bit-identical to
// the verified round-16 permutation).
__global__ __launch_bounds__(128) void prep_kernel(const int* __restrict__ adj,
                                                   const float* __restrict__ x) {
  int bi = blockIdx.x;
  int i  = bi & (NN - 1);
  const int4* row4 = (const int4*)(adj + (size_t)bi * NN);
  int tid = threadIdx.x;
  unsigned word = 0u;
#pragma unroll
  for (int s = 0; s < 8; s++) {
    int4 v = row4[tid * 8 + s];
    unsigned m = (unsigned)v.x + ((unsigned)v.y << 1) +
                 ((unsigned)v.z << 2) + ((unsigned)v.w << 3);
    word += m << (s * 4);
  }
  if ((i >> 5) == tid) word |= 1u << (i & 31);   // self loop (orig bit order)

  int cnt = __popc(word);

  // pair-transpose permute (== old byte gather), 2 delta swaps
  unsigned y = ((word >> 12) ^ word) & 0x0000F0F0u;
  word ^= y ^ (y << 12);
  y = ((word >> 6) ^ word) & 0x00CC00CCu;
  word ^= y ^ (y << 6);
  g_Ap[(size_t)bi * 128 + tid] = word;

  __shared__ int red[4];
  int wsum = __reduce_add_sync(0xffffffffu, cnt);
  if ((tid & 31) == 0) red[tid >> 5] = wsum;
  __syncthreads();
  float dv = rsqrtf((float)(red[0] + red[1] + red[2] + red[3]));
  if (tid == 0) g_dinv[bi] = dv;
  // fused scalex: t0[j][d] = fp16(dinv_j * x[j][d])
  if (tid < 64)
    g_tb[0][(size_t)bi * 64 + tid] =
        __float2half(x[(size_t)bi * 64 + tid] * dv);
}

// ---------------- kernel 2: fused  out = dinv_i*(A@t)@W + b [; elu; drop] ---
// M-tile = 128, K-chunk = 128, 512 threads, warp grid (m4, k2, n2).
// A stays packed (cp.async-staged 2KB); fragments via PRMT + x0x8001 spread;
// '1' encoded as fp16 subnormal 0x0001 (2^-24), compensated in epilogue.
// B staged via cp.async double buffering overlapping MMAs.
#define BS_STRIDE 72
#define OFF_B0 0
#define OFF_B1 18432
#define OFF_AP0 36864
#define OFF_AP1 38912
#define OFF_WHI 40960
#define OFF_WLO 50176
#define OFF_CS  59392
#define AGG_DYN 77824

__global__ __launch_bounds__(512, 1) void agg_kernel(
    const float* __restrict__ Wm, const float* __restrict__ bias,
    float* __restrict__ outp, int tin_sel,
    unsigned ka, unsigned kb, int do_drop) {
  extern __shared__ __align__(16) char smem[];
  __half* Whi = (__half*)(smem + OFF_WHI);
  __half* Wlo = (__half*)(smem + OFF_WLO);

  int tid = threadIdx.x, wid = tid >> 5, lane = tid & 31;
  // mainloop warp grid: m4 x k2 x n2
  int wm = wid >> 2, kg = (wid >> 1) & 1, wn = wid & 1;
  int b = blockIdx.y, i0 = blockIdx.x * 128;

  // W hi/lo split
#pragma unroll
  for (int s = 0; s < 8; s++) {
    int idx = tid + 512 * s;
    int r = idx >> 6, c = idx & 63;
    float w = Wm[idx];
    __half hh = __float2half(w);
    Whi[r * BS_STRIDE + c] = hh;
    Wlo[r * BS_STRIDE + c] = __float2half(w - __half2float(hh));
  }

  const unsigned* Ap = g_Ap + ((size_t)b * NN + i0) * 128;
  const __half* tin = g_tb[tin_sel] + (size_t)b * NN * DD;
  __half* tout = g_tb[tin_sel ^ 1] + (size_t)b * NN * DD;

  unsigned sbase = smem_u32(smem);

  float acc[2][4][4];
#pragma unroll
  for (int mt = 0; mt < 2; mt++)
#pragma unroll
    for (int nt = 0; nt < 4; nt++)
#pragma unroll
      for (int q = 0; q < 4; q++) acc[mt][nt][q] = 0.0f;

  int lr = lane & 15, lc8 = (lane >> 4) << 3;
  unsigned psel = 0x4440u | (unsigned)(lane & 3);  // PRMT byte-extract selector
  int fr0 = wm * 32 + (lane >> 2);     // mt=0 rows: fr0, fr0+8 ; mt=1: +16

  // precomputed ldsm B base addresses (per buffer)
  unsigned bb0 = sbase + OFF_B0 + (unsigned)((kg * 64 + lr) * 144 +
                                             (wn * 32 + lc8) * 2);
  unsigned bb1 = bb0 + (OFF_B1 - OFF_B0);

  // cp.async staging of one chunk into buffer `buf`
  auto stage = [&](int c, int buf) {
    if (tid < 128)
      cp16(sbase + (buf ? OFF_AP1 : OFF_AP0) + tid * 16,
           Ap + (size_t)tid * 128 + c * 4);
#pragma unroll
    for (int s = 0; s < 2; s++) {
      int q = tid + 512 * s;
      cp16(sbase + (buf ? OFF_B1 : OFF_B0) + (q >> 3) * 144 + (q & 7) * 16,
           tin + (size_t)(c * 128 + (q >> 3)) * DD + (q & 7) * 8);
    }
  };

  stage(0, 0);
  cp_commit();

  for (int c = 0; c < 32; c++) {
    int cur = c & 1;
    cp_wait0();
    __syncthreads();
    if (c < 31) { stage(c + 1, cur ^ 1); cp_commit(); }

    char* apbuf = smem + (cur ? OFF_AP1 : OFF_AP0);
    unsigned bbc = cur ? bb1 : bb0;

    // pull this warp's packed K64 slice, extract byte, multiply-spread
    unsigned spr[2][2][2];   // [mt][rowA/rowB][word]
#pragma unroll
    for (int mt = 0; mt < 2; mt++) {
      int ra = fr0 + mt * 16;
      uint2 wa2 = *(uint2*)(apbuf + ra * 16 + kg * 8);
      uint2 wb2 = *(uint2*)(apbuf + (ra + 8) * 16 + kg * 8);
      spr[mt][0][0] = __byte_perm(wa2.x, 0u, psel) * 0x8001u;
      spr[mt][0][1] = __byte_perm(wa2.y, 0u, psel) * 0x8001u;
      spr[mt][1][0] = __byte_perm(wb2.x, 0u, psel) * 0x8001u;
      spr[mt][1][1] = __byte_perm(wb2.y, 0u, psel) * 0x8001u;
    }
    // MMA on current buffer: warp's K-slice = [kg*64, kg*64+64)
#pragma unroll
    for (int ks = 0; ks < 4; ks++) {
      unsigned bf[2][4];
      unsigned baddr = bbc + (unsigned)(ks * 16 * 144);
      ldsm_x4ta(bf[0], baddr);
      ldsm_x4ta(bf[1], baddr + 32);
      unsigned a[2][4];
      int sh = (ks & 1) * 4;
#pragma unroll
      for (int mt = 0; mt < 2; mt++) {
        unsigned sa = spr[mt][0][ks >> 1];
        unsigned sb = spr[mt][1][ks >> 1];
        a[mt][0] = (sa >> sh) & 0x00010001u;
        a[mt][1] = (sb >> sh) & 0x00010001u;
        a[mt][2] = (sa >> (sh + 2)) & 0x00010001u;
        a[mt][3] = (sb >> (sh + 2)) & 0x00010001u;
      }
#pragma unroll
      for (int mt = 0; mt < 2; mt++)
#pragma unroll
        for (int nt = 0; nt < 4; nt++)
          mma16816(acc[mt][nt], a[mt],
                   bf[nt >> 1][(nt & 1) * 2], bf[nt >> 1][(nt & 1) * 2 + 1]);
    }
  }
  __syncthreads();

  // ---- cross-kg reduction + Cs = fp16(2^24 * dinv_i * C) --------------------
  float* Rs = (float*)(smem + OFF_B0);          // 128 x 68 fp32 (34816 B)
  __half* Cs = (__half*)(smem + OFF_CS);        // 128 x 72 fp16 (18432 B)
  int g = lane >> 2, tig = lane & 3;

  if (kg == 1) {
#pragma unroll
    for (int mt = 0; mt < 2; mt++)
#pragma unroll
      for (int hr = 0; hr < 2; hr++) {
        int il = wm * 32 + mt * 16 + g + hr * 8;
#pragma unroll
        for (int nt = 0; nt < 4; nt++) {
          int col = wn * 32 + nt * 8 + tig * 2;
          *(float2*)&Rs[il * 68 + col] =
              make_float2(acc[mt][nt][hr * 2], acc[mt][nt][hr * 2 + 1]);
        }
      }
  }
  __syncthreads();
  if (kg == 0) {
#pragma unroll
    for (int mt = 0; mt < 2; mt++)
#pragma unroll
      for (int hr = 0; hr < 2; hr++) {
        int il = wm * 32 + mt * 16 + g + hr * 8;
        // compensate the 2^-24 subnormal encoding of A here (exact pow2)
        float dv = g_dinv[b * NN + i0 + il] * 16777216.0f;
#pragma unroll
        for (int nt = 0; nt < 4; nt++) {
          int col = wn * 32 + nt * 8 + tig * 2;
          float2 r = *(float2*)&Rs[il * 68 + col];
          __half2 hv =
              __floats2half2_rn((acc[mt][nt][hr * 2] + r.x) * dv,
                                (acc[mt][nt][hr * 2 + 1] + r.y) * dv);
          *(__half2*)&Cs[il * BS_STRIDE + col] = hv;
        }
      }
  }
  __syncthreads();

  // W-multiply: D = Cs @ (Whi + Wlo); warp grid m4 x n4, tile M32 x N16, K=64
  int warp_m = wid >> 2, warp_n = wid & 3;
  float acc2[2][2][4];
#pragma unroll
  for (int mt = 0; mt < 2; mt++)
#pragma unroll
    for (int nt = 0; nt < 2; nt++)
#pragma unroll
      for (int q = 0; q < 4; q++) acc2[mt][nt][q] = 0.0f;

#pragma unroll
  for (int ks = 0; ks < 4; ks++) {
    unsigned a2[2][4], bh[4], bl[4];
#pragma unroll
    for (int mt = 0; mt < 2; mt++)
      ldsm_x4(a2[mt], &Cs[(warp_m * 32 + mt * 16 + lr) * BS_STRIDE + ks * 16 + lc8]);
    ldsm_x4_t(bh, &Whi[(ks * 16 + lr) * BS_STRIDE + warp_n * 16 + lc8]);
    ldsm_x4_t(bl, &Wlo[(ks * 16 + lr) * BS_STRIDE + warp_n * 16 + lc8]);
#pragma unroll
    for (int mt = 0; mt < 2; mt++)
#pragma unroll
      for (int nt = 0; nt < 2; nt++) {
        mma16816(acc2[mt][nt], a2[mt], bh[nt * 2], bh[nt * 2 + 1]);
        mma16816(acc2[mt][nt], a2[mt], bl[nt * 2], bl[nt * 2 + 1]);
      }
  }

  // final epilogue
#pragma unroll
  for (int mt = 0; mt < 2; mt++) {
#pragma unroll
    for (int hr = 0; hr < 2; hr++) {
      int i = i0 + warp_m * 32 + mt * 16 + g + hr * 8;
      float dv = g_dinv[b * NN + i];
#pragma unroll
      for (int nt = 0; nt < 2; nt++) {
#pragma unroll
        for (int c2 = 0; c2 < 2; c2++) {
          int col = warp_n * 16 + nt * 8 + tig * 2 + c2;
          float v = acc2[mt][nt][hr * 2 + c2] + __ldg(&bias[col]);
          unsigned idx = ((unsigned)(b * NN + i)) * 64u + (unsigned)col;
          if (do_drop) {
            v = (v > 0.0f) ? v : expm1f(v);      // ELU
            v = drop_apply(v, idx, ka, kb);      // JAX threefry dropout
            tout[(size_t)i * DD + col] = __float2half(v * dv);
          } else {
            outp[idx] = v;
          }
        }
      }
    }
  }
}

// ---------------- launch ----------------------------------------------------
extern "C" void kernel_launch(void* const* d_in, const int* in_sizes, int n_in,
                              void* d_out, int out_size) {
  const float* x  = (const float*)d_in[0];
  const int*   adj= (const int*)d_in[1];
  const float* W1 = (const float*)d_in[2];
  const float* b1 = (const float*)d_in[3];
  const float* W2 = (const float*)d_in[4];
  const float* b2 = (const float*)d_in[5];
  const float* W3 = (const float*)d_in[6];
  const float* b3 = (const float*)d_in[7];
  float* out = (float*)d_out;

  (void)in_sizes; (void)n_in; (void)out_size;

  cudaFuncSetAttribute(agg_kernel, cudaFuncAttributeMaxDynamicSharedMemorySize,
                       AGG_DYN);

  prep_kernel<<<BB * NN, 128>>>(adj, x);

  dim3 agrid(NN / 128, BB);
  agg_kernel<<<agrid, 512, AGG_DYN>>>(W1, b1, nullptr, 0, cK1.a, cK1.b, 1);
  agg_kernel<<<agrid, 512, AGG_DYN>>>(W2, b2, nullptr, 1, cK2.a, cK2.b, 1);
  agg_kernel<<<agrid, 512, AGG_DYN>>>(W3, b3, out, 0, 0u, 0u, 0);
}